// round 13
// baseline (speedup 1.0000x reference)
#include <cuda_runtime.h>
#include <cstdint>

namespace {

constexpr int CIN  = 64;
constexpr int H    = 56;
constexpr int W    = 56;
constexpr int OC   = 64;
constexpr int TH   = 4;            // output rows per block
constexpr int NR   = TH + 2;       // x rows staged (halo)
constexpr int NTHR = 448;          // 14 warps; warp id == width group

constexpr int WS_ELEMS = 32 * 3 * 3 * OC;       // 18432 floats
constexpr int TSTRIDE  = 68;                    // padded row (cols 0..57 T, 64..66 w0-specials)
constexpr int T_ELEMS  = 32 * NR * TSTRIDE;     // 13056 floats
constexpr int XS_ELEMS = NR * CIN * W;          // 21504 floats
constexpr int WS_OFF   = 0;
constexpr int T_OFF    = WS_ELEMS;
constexpr int XS_OFF   = WS_ELEMS + T_ELEMS;
constexpr int SMEM_BYTES = (WS_ELEMS + T_ELEMS + XS_ELEMS) * 4;  // 211968 B

__device__ __forceinline__ uint64_t bcast_f32x2(float s) {
    uint64_t r;
    asm("mov.b64 %0, {%1, %1};" : "=l"(r) : "f"(s));
    return r;
}
__device__ __forceinline__ void fma_f32x2(uint64_t& d, uint64_t a, uint64_t b) {
    asm("fma.rn.f32x2 %0, %1, %2, %0;" : "+l"(d) : "l"(a), "l"(b));
}

// Inner mainloop over (l, j, k). W0SPECIAL: this warp owns w0==0 (uses special q=0 taps).
template <bool W0SPECIAL>
__device__ __forceinline__ void mainloop(const float* __restrict__ Tm,
                                         const float* __restrict__ ws,
                                         int hh, int w0, int i0,
                                         uint64_t acc2[4][4])
{
    for (int l = 0; l < 32; ++l) {
        #pragma unroll
        for (int j = 0; j < 3; ++j) {
            const float* trow = Tm + (l * NR + hh + j) * TSTRIDE;
            float4 t03 = *reinterpret_cast<const float4*>(trow + w0);
            float2 t45 = *reinterpret_cast<const float2*>(trow + w0 + 4);
            uint64_t bs[6];
            bs[0] = bcast_f32x2(t03.x);
            bs[1] = bcast_f32x2(t03.y);
            bs[2] = bcast_f32x2(t03.z);
            bs[3] = bcast_f32x2(t03.w);
            bs[4] = bcast_f32x2(t45.x);
            bs[5] = bcast_f32x2(t45.y);

            uint64_t q0[3];
            if (W0SPECIAL) {
                float4 sp = *reinterpret_cast<const float4*>(trow + 64);
                q0[0] = bcast_f32x2(sp.x);
                q0[1] = bcast_f32x2(sp.y);
                q0[2] = bcast_f32x2(sp.z);
            } else {
                q0[0] = bs[0]; q0[1] = bs[1]; q0[2] = bs[2];
            }

            const float* wrow = ws + ((l * 3 + j) * 3) * OC + i0;
            #pragma unroll
            for (int k = 0; k < 3; ++k) {
                ulonglong2 wp01 = *reinterpret_cast<const ulonglong2*>(wrow + k * OC);
                ulonglong2 wp23 = *reinterpret_cast<const ulonglong2*>(wrow + k * OC + 4);
                const uint64_t wp[4] = {wp01.x, wp01.y, wp23.x, wp23.y};
                #pragma unroll
                for (int p = 0; p < 4; ++p) {
                    fma_f32x2(acc2[p][0], wp[p], q0[k]);
                    fma_f32x2(acc2[p][1], wp[p], bs[k + 1]);
                    fma_f32x2(acc2[p][2], wp[p], bs[k + 2]);
                    fma_f32x2(acc2[p][3], wp[p], bs[k + 3]);
                }
            }
        }
    }
}

// y[b,i,h,w] = sum_{l,j,k} w[l,j,k,i] * s(b,l,k,h+j-1,w)
// s(b,l,k,h',w) = A(l,h',w+k-1) + A(l+32,h',((w-1)%W)+k-1)
// A(c,h',u) = (0<=u<W) ? x[b,c,h',(u-1+W)%W] : 0 ; h' outside [0,H) -> 0
// Precompute T[l,row,t] = A(l,·,t-1) + A(l+32,·,t-2); then s = T[w+k] for w>=1.
// w==0 special taps stored at T cols 64..66.
__global__ __launch_bounds__(NTHR, 1)
void shift_conv_kernel(const float* __restrict__ x,
                       const float* __restrict__ wt,
                       float* __restrict__ y)
{
    extern __shared__ float smem[];
    float* ws = smem + WS_OFF;   // [288][OC], same linear layout as wt
    float* Tm = smem + T_OFF;    // [32][NR][TSTRIDE]
    float* xs = smem + XS_OFF;   // [NR][CIN][W] (staging; dead after T build)

    const int b   = blockIdx.y;
    const int h0  = blockIdx.x * TH;
    const int tid = threadIdx.x;

    // Stage all weights (layout matches global exactly)
    for (int idx = tid; idx < WS_ELEMS; idx += NTHR) ws[idx] = wt[idx];

    // Stage 6 x rows (zero-filled outside [0,H)) as float4
    const float* xb = x + (size_t)b * CIN * H * W;
    for (int idx = tid; idx < NR * CIN * (W / 4); idx += NTHR) {
        int f4 = idx % (W / 4);
        int rc = idx / (W / 4);
        int c  = rc % CIN;
        int rr = rc / CIN;
        int hp = h0 - 1 + rr;
        float4 v = make_float4(0.f, 0.f, 0.f, 0.f);
        if (0 <= hp && hp < H)
            v = *reinterpret_cast<const float4*>(xb + ((size_t)c * H + hp) * W + f4 * 4);
        *reinterpret_cast<float4*>(xs + (rr * CIN + c) * W + f4 * 4) = v;
    }
    __syncthreads();

    // Build T: per (l,row): cols 0..57 regular window, 3 specials at 64..66.
    //  T[t] = A(l,t-1) + A(l+32,t-2)
    //   A(l,t-1):    nonzero iff 1<=t<=56,  value xl[(t-2+W)%W]
    //   A(l+32,t-2): nonzero iff 2<=t<=57,  value xh[(t-3+W)%W]
    //  specials (w=0): k=0: xh[W-3]; k=1: xl[W-1]+xh[W-2]; k=2: xl[0]
    for (int e = tid; e < 32 * NR * 61; e += NTHR) {
        int rcol = e % 61;
        int rowi = e / 61;             // l*NR + rr
        int l  = rowi / NR;
        int rr = rowi % NR;
        const float* xl = xs + (rr * CIN + l) * W;
        const float* xh = xs + (rr * CIN + l + 32) * W;
        float v;
        int col;
        if (rcol < 58) {
            int t = rcol;
            float a = 0.f, bb = 0.f;
            if (t >= 1 && t <= 56) { int u = t - 2; if (u < 0) u += W; a  = xl[u]; }
            if (t >= 2)            { int u = t - 3; if (u < 0) u += W; bb = xh[u]; }
            v = a + bb;
            col = t;
        } else {
            int k = rcol - 58;
            if (k == 0)      v = xh[W - 3];
            else if (k == 1) v = xl[W - 1] + xh[W - 2];
            else             v = xl[0];
            col = 64 + k;
        }
        Tm[rowi * TSTRIDE + col] = v;
    }
    __syncthreads();

    // Thread mapping: warp == width group (w0 uniform per warp); lane -> (ig, hh)
    const int wg   = tid >> 5;       // 0..13
    const int lane = tid & 31;
    const int ig   = lane & 7;       // 8 outch groups
    const int hh   = lane >> 3;      // 4 output rows
    const int i0   = ig * 8;
    const int w0   = wg * 4;
    const int h    = h0 + hh;

    // acc2[p][q]: packed pair (outch i0+2p lo, i0+2p+1 hi), width w0+q
    uint64_t acc2[4][4];
    #pragma unroll
    for (int p = 0; p < 4; ++p)
        #pragma unroll
        for (int q = 0; q < 4; ++q) acc2[p][q] = 0ull;

    if (wg == 0) mainloop<true >(Tm, ws, hh, w0, i0, acc2);
    else         mainloop<false>(Tm, ws, hh, w0, i0, acc2);

    float* yb = y + (((size_t)b * OC + i0) * H + h) * W + w0;
    #pragma unroll
    for (int p = 0; p < 4; ++p) {
        float4 vlo, vhi;
        float* plo = &vlo.x;
        float* phi = &vhi.x;
        #pragma unroll
        for (int q = 0; q < 4; ++q) {
            plo[q] = __uint_as_float((unsigned)(acc2[p][q] & 0xffffffffu));
            phi[q] = __uint_as_float((unsigned)(acc2[p][q] >> 32));
        }
        *reinterpret_cast<float4*>(yb + (size_t)(2 * p)     * H * W) = vlo;
        *reinterpret_cast<float4*>(yb + (size_t)(2 * p + 1) * H * W) = vhi;
    }
}

} // namespace

extern "C" void kernel_launch(void* const* d_in, const int* in_sizes, int n_in,
                              void* d_out, int out_size)
{
    const float* x  = (const float*)d_in[0];   // [1024,64,56,56] f32
    const float* wt = (const float*)d_in[1];   // [32,3,3,64] f32
    float* y = (float*)d_out;                  // [1024,64,56,56] f32

    cudaFuncSetAttribute(shift_conv_kernel,
                         cudaFuncAttributeMaxDynamicSharedMemorySize, SMEM_BYTES);
    dim3 grid(H / TH, 1024, 1);
    shift_conv_kernel<<<grid, NTHR, SMEM_BYTES>>>(x, wt, y);
}

// round 16
// speedup vs baseline: 1.3978x; 1.3978x over previous
#include <cuda_runtime.h>
#include <cstdint>

namespace {

constexpr int CIN  = 64;
constexpr int H    = 56;
constexpr int W    = 56;
constexpr int OC   = 64;
constexpr int TH   = 4;            // output rows per block
constexpr int NR   = TH + 2;       // x rows staged (halo)
constexpr int NTHR = 512;          // R3-proven mapping: lane -> wg, warp-uniform trow

constexpr int WS_ELEMS = 32 * 3 * 3 * OC;       // 18432 floats
constexpr int TSTRIDE  = 68;                    // cols 0..57 window, 64..66 w0-specials
constexpr int T_ELEMS  = 32 * NR * TSTRIDE;     // 13056 floats
constexpr int XS_ELEMS = NR * CIN * W;          // 21504 floats
constexpr int WS_OFF   = 0;
constexpr int T_OFF    = WS_ELEMS;
constexpr int XS_OFF   = WS_ELEMS + T_ELEMS;
constexpr int SMEM_BYTES = (WS_ELEMS + T_ELEMS + XS_ELEMS) * 4;  // 211968 B

__device__ __forceinline__ uint64_t bcast_f32x2(float s) {
    uint64_t r;
    asm("mov.b64 %0, {%1, %1};" : "=l"(r) : "f"(s));
    return r;
}
__device__ __forceinline__ void fma_f32x2(uint64_t& d, uint64_t a, uint64_t b) {
    asm("fma.rn.f32x2 %0, %1, %2, %0;" : "+l"(d) : "l"(a), "l"(b));
}

// y[b,i,h,w] = sum_{l,j,k} w[l,j,k,i] * s(b,l,k,h+j-1,w)
// Precomputed T[l,row,t] = A(l,row,t-1) + A(l+32,row,t-2); s(w,k) = T[w+k] for w>=1.
// w==0 special taps at T cols 64..66: {xh[W-3], xl[W-1]+xh[W-2], xl[0]}.
__global__ __launch_bounds__(NTHR, 1)
void shift_conv_kernel(const float* __restrict__ x,
                       const float* __restrict__ wt,
                       float* __restrict__ y)
{
    extern __shared__ float smem[];
    float* ws = smem + WS_OFF;   // [288][OC], same linear layout as wt
    float* Tm = smem + T_OFF;    // [32][NR][TSTRIDE]
    float* xs = smem + XS_OFF;   // [NR][CIN][W] staging (dead after T build)

    const int b   = blockIdx.y;
    const int h0  = blockIdx.x * TH;
    const int tid = threadIdx.x;

    // Stage all weights (layout matches global exactly)
    for (int idx = tid; idx < WS_ELEMS; idx += NTHR) ws[idx] = wt[idx];

    // Stage 6 x rows (zero-filled outside [0,H)) as float4
    const float* xb = x + (size_t)b * CIN * H * W;
    for (int idx = tid; idx < NR * CIN * (W / 4); idx += NTHR) {
        int f4 = idx % (W / 4);
        int rc = idx / (W / 4);
        int c  = rc % CIN;
        int rr = rc / CIN;
        int hp = h0 - 1 + rr;
        float4 v = make_float4(0.f, 0.f, 0.f, 0.f);
        if (0 <= hp && hp < H)
            v = *reinterpret_cast<const float4*>(xb + ((size_t)c * H + hp) * W + f4 * 4);
        *reinterpret_cast<float4*>(xs + (rr * CIN + c) * W + f4 * 4) = v;
    }
    __syncthreads();

    // Build T: cols 0..57 regular window, specials at 64..66.
    //  T[t] = A(l,t-1) + A(l+32,t-2)
    //   A(l,t-1):    nonzero iff 1<=t<=56, value xl[(t-2+W)%W]
    //   A(l+32,t-2): nonzero iff 2<=t<=57, value xh[(t-3+W)%W]
    //  specials (w=0): k=0: xh[W-3]; k=1: xl[W-1]+xh[W-2]; k=2: xl[0]
    for (int e = tid; e < 32 * NR * 61; e += NTHR) {
        int rcol = e % 61;
        int rowi = e / 61;             // l*NR + rr
        int l  = rowi / NR;
        int rr = rowi % NR;
        const float* xl = xs + (rr * CIN + l) * W;
        const float* xh = xs + (rr * CIN + l + 32) * W;
        float v;
        int col;
        if (rcol < 58) {
            int t = rcol;
            float a = 0.f, bb = 0.f;
            if (t >= 1 && t <= 56) { int u = t - 2; if (u < 0) u += W; a  = xl[u]; }
            if (t >= 2)            { int u = t - 3; if (u < 0) u += W; bb = xh[u]; }
            v = a + bb;
            col = t;
        } else {
            int k = rcol - 58;
            if (k == 0)      v = xh[W - 3];
            else if (k == 1) v = xl[W - 1] + xh[W - 2];
            else             v = xl[0];
            col = 64 + k;
        }
        Tm[rowi * TSTRIDE + col] = v;
    }
    __syncthreads();

    // R3-proven thread mapping: hh = tid>>7 (x-row), ig = 8-outch group, wg = 4-wide w group.
    // Within a warp: ig takes 2 values (weight loads 2-distinct -> broadcast),
    // trow is warp-uniform, stores are coalesced across wg.
    const int hh = tid >> 7;
    const int r  = tid & 127;
    const int ig = r >> 4;
    const int wg = r & 15;
    if (wg >= 14) return;           // no further __syncthreads below

    const int  i0     = ig * 8;
    const int  w0     = wg * 4;
    const int  h      = h0 + hh;
    const bool w0zero = (w0 == 0);

    // acc2[p][q]: packed outch pair (i0+2p lo, i0+2p+1 hi), width w0+q
    uint64_t acc2[4][4];
    #pragma unroll
    for (int p = 0; p < 4; ++p)
        #pragma unroll
        for (int q = 0; q < 4; ++q) acc2[p][q] = 0ull;

    for (int l = 0; l < 32; ++l) {
        #pragma unroll
        for (int j = 0; j < 3; ++j) {
            const float* trow = Tm + (l * NR + hh + j) * TSTRIDE;
            float4 t03 = *reinterpret_cast<const float4*>(trow + w0);
            float2 t45 = *reinterpret_cast<const float2*>(trow + w0 + 4);
            float4 sp  = *reinterpret_cast<const float4*>(trow + 64);  // warp-uniform bcast

            // q slot 0 (width w0) uses special taps iff w0==0; others use the window.
            float q0f0 = w0zero ? sp.x : t03.x;
            float q0f1 = w0zero ? sp.y : t03.y;
            float q0f2 = w0zero ? sp.z : t03.z;
            uint64_t q0[3] = {bcast_f32x2(q0f0), bcast_f32x2(q0f1), bcast_f32x2(q0f2)};
            uint64_t bs1 = bcast_f32x2(t03.y);
            uint64_t bs2 = bcast_f32x2(t03.z);
            uint64_t bs3 = bcast_f32x2(t03.w);
            uint64_t bs4 = bcast_f32x2(t45.x);
            uint64_t bs5 = bcast_f32x2(t45.y);
            const uint64_t bsv[6] = {0ull, bs1, bs2, bs3, bs4, bs5};

            const float* wrow = ws + ((l * 3 + j) * 3) * OC + i0;
            #pragma unroll
            for (int k = 0; k < 3; ++k) {
                ulonglong2 wp01 = *reinterpret_cast<const ulonglong2*>(wrow + k * OC);
                ulonglong2 wp23 = *reinterpret_cast<const ulonglong2*>(wrow + k * OC + 4);
                const uint64_t wp[4] = {wp01.x, wp01.y, wp23.x, wp23.y};
                #pragma unroll
                for (int p = 0; p < 4; ++p) {
                    fma_f32x2(acc2[p][0], wp[p], q0[k]);
                    fma_f32x2(acc2[p][1], wp[p], bsv[k + 1]);
                    fma_f32x2(acc2[p][2], wp[p], bsv[k + 2]);
                    fma_f32x2(acc2[p][3], wp[p], bsv[k + 3]);
                }
            }
        }
    }

    // Coalesced stores (R3 layout): lanes sweep wg -> contiguous 16B chunks per ig half.
    float* yb = y + (((size_t)b * OC + i0) * H + h) * W + w0;
    #pragma unroll
    for (int p = 0; p < 4; ++p) {
        float4 vlo, vhi;
        float* plo = &vlo.x;
        float* phi = &vhi.x;
        #pragma unroll
        for (int q = 0; q < 4; ++q) {
            plo[q] = __uint_as_float((unsigned)(acc2[p][q] & 0xffffffffu));
            phi[q] = __uint_as_float((unsigned)(acc2[p][q] >> 32));
        }
        *reinterpret_cast<float4*>(yb + (size_t)(2 * p)     * H * W) = vlo;
        *reinterpret_cast<float4*>(yb + (size_t)(2 * p + 1) * H * W) = vhi;
    }
}

} // namespace

extern "C" void kernel_launch(void* const* d_in, const int* in_sizes, int n_in,
                              void* d_out, int out_size)
{
    const float* x  = (const float*)d_in[0];   // [1024,64,56,56] f32
    const float* wt = (const float*)d_in[1];   // [32,3,3,64] f32
    float* y = (float*)d_out;                  // [1024,64,56,56] f32

    cudaFuncSetAttribute(shift_conv_kernel,
                         cudaFuncAttributeMaxDynamicSharedMemorySize, SMEM_BYTES);
    dim3 grid(H / TH, 1024, 1);
    shift_conv_kernel<<<grid, NTHR, SMEM_BYTES>>>(x, wt, y);
}

// round 17
// speedup vs baseline: 1.5096x; 1.0800x over previous
#include <cuda_runtime.h>
#include <cstdint>

namespace {

constexpr int CIN  = 64;
constexpr int H    = 56;
constexpr int W    = 56;
constexpr int OC   = 64;
constexpr int TH   = 4;            // output rows per block
constexpr int NR   = TH + 2;       // halo rows
constexpr int NTHR = 448;          // 4 (hh) x 8 (ig) x 14 (wg), exact

constexpr int TSTRIDE  = 68;                    // cols 0..57 window, 64..66 w0-specials
constexpr int T_ELEMS  = 32 * NR * TSTRIDE;     // 13056 floats
constexpr int SMEM_BYTES = T_ELEMS * 4;         // 52224 B -> 2 CTAs/SM

__device__ __forceinline__ uint64_t bcast_f32x2(float s) {
    uint64_t r;
    asm("mov.b64 %0, {%1, %1};" : "=l"(r) : "f"(s));
    return r;
}
__device__ __forceinline__ void fma_f32x2(uint64_t& d, uint64_t a, uint64_t b) {
    asm("fma.rn.f32x2 %0, %1, %2, %0;" : "+l"(d) : "l"(a), "l"(b));
}

// y[b,i,h,w] = sum_{l,j,k} w[l,j,k,i] * s(b,l,k,h+j-1,w)
// T[l,row,t] = A(l,row,t-1) + A(l+32,row,t-2); s(w,k) = T[w+k] for w>=1.
// w==0 special taps at T cols 64..66: {xh[W-3], xl[W-1]+xh[W-2], xl[0]}.
// Weights are read via LDG (L1/L2-resident, shared by all CTAs) - no smem copy.
__global__ __launch_bounds__(NTHR, 2)
void shift_conv_kernel(const float* __restrict__ x,
                       const float* __restrict__ wt,
                       float* __restrict__ y)
{
    extern __shared__ float smem[];
    float* Tm = smem;            // [32][NR][TSTRIDE]

    const int b   = blockIdx.y;
    const int h0  = blockIdx.x * TH;
    const int tid = threadIdx.x;

    const float* xb = x + (size_t)b * CIN * H * W;

    // Build T directly from global x (coalesced along rcol; h-halo rows -> 0).
    //  T[t] = A(l,t-1) + A(l+32,t-2)
    //   A(l,t-1):    nonzero iff 1<=t<=56, value xl[(t-2+W)%W]
    //   A(l+32,t-2): nonzero iff 2<=t<=57, value xh[(t-3+W)%W]
    //  specials (w=0): k=0: xh[W-3]; k=1: xl[W-1]+xh[W-2]; k=2: xl[0]
    for (int e = tid; e < 32 * NR * 61; e += NTHR) {
        int rcol = e % 61;
        int rowi = e / 61;             // l*NR + rr
        int l  = rowi / NR;
        int rr = rowi % NR;
        int hp = h0 - 1 + rr;
        float v = 0.f;
        int col;
        if (rcol < 58) col = rcol; else col = 64 + (rcol - 58);
        if (0 <= hp && hp < H) {
            const float* xl = xb + ((size_t)l        * H + hp) * W;
            const float* xh = xb + ((size_t)(l + 32) * H + hp) * W;
            if (rcol < 58) {
                int t = rcol;
                float a = 0.f, bb = 0.f;
                if (t >= 1 && t <= 56) { int u = t - 2; if (u < 0) u += W; a  = xl[u]; }
                if (t >= 2)            { int u = t - 3; if (u < 0) u += W; bb = xh[u]; }
                v = a + bb;
            } else {
                int k = rcol - 58;
                if (k == 0)      v = xh[W - 3];
                else if (k == 1) v = xl[W - 1] + xh[W - 2];
                else             v = xl[0];
            }
        }
        Tm[rowi * TSTRIDE + col] = v;
    }
    __syncthreads();

    // Mapping: hh = tid/112 (x-row), ig = 8-outch group, wg = 4-wide w group.
    // Weight LDG addresses are 2-3-distinct per warp (broadcast-friendly);
    // stores coalesce across wg.
    const int hh = tid / 112;
    const int r  = tid % 112;
    const int ig = r / 14;
    const int wg = r % 14;

    const int  i0     = ig * 8;
    const int  w0     = wg * 4;
    const int  h      = h0 + hh;
    const bool w0zero = (w0 == 0);

    // acc2[p][q]: packed outch pair (i0+2p lo, i0+2p+1 hi), width w0+q
    uint64_t acc2[4][4];
    #pragma unroll
    for (int p = 0; p < 4; ++p)
        #pragma unroll
        for (int q = 0; q < 4; ++q) acc2[p][q] = 0ull;

    for (int l = 0; l < 32; ++l) {
        #pragma unroll
        for (int j = 0; j < 3; ++j) {
            const float* trow = Tm + (l * NR + hh + j) * TSTRIDE;
            float4 t03 = *reinterpret_cast<const float4*>(trow + w0);
            float2 t45 = *reinterpret_cast<const float2*>(trow + w0 + 4);
            float4 sp  = *reinterpret_cast<const float4*>(trow + 64);  // near-uniform bcast

            float q0f0 = w0zero ? sp.x : t03.x;
            float q0f1 = w0zero ? sp.y : t03.y;
            float q0f2 = w0zero ? sp.z : t03.z;
            uint64_t q0[3] = {bcast_f32x2(q0f0), bcast_f32x2(q0f1), bcast_f32x2(q0f2)};
            uint64_t bs1 = bcast_f32x2(t03.y);
            uint64_t bs2 = bcast_f32x2(t03.z);
            uint64_t bs3 = bcast_f32x2(t03.w);
            uint64_t bs4 = bcast_f32x2(t45.x);
            uint64_t bs5 = bcast_f32x2(t45.y);
            const uint64_t bsv[6] = {0ull, bs1, bs2, bs3, bs4, bs5};

            const float* wrow = wt + ((l * 3 + j) * 3) * OC + i0;  // global (L1/L2-hot)
            #pragma unroll
            for (int k = 0; k < 3; ++k) {
                ulonglong2 wp01 = *reinterpret_cast<const ulonglong2*>(wrow + k * OC);
                ulonglong2 wp23 = *reinterpret_cast<const ulonglong2*>(wrow + k * OC + 4);
                const uint64_t wp[4] = {wp01.x, wp01.y, wp23.x, wp23.y};
                #pragma unroll
                for (int p = 0; p < 4; ++p) {
                    fma_f32x2(acc2[p][0], wp[p], q0[k]);
                    fma_f32x2(acc2[p][1], wp[p], bsv[k + 1]);
                    fma_f32x2(acc2[p][2], wp[p], bsv[k + 2]);
                    fma_f32x2(acc2[p][3], wp[p], bsv[k + 3]);
                }
            }
        }
    }

    // Coalesced stores: lanes sweep wg -> contiguous 16B chunks per ig run.
    float* yb = y + (((size_t)b * OC + i0) * H + h) * W + w0;
    #pragma unroll
    for (int p = 0; p < 4; ++p) {
        float4 vlo, vhi;
        float* plo = &vlo.x;
        float* phi = &vhi.x;
        #pragma unroll
        for (int q = 0; q < 4; ++q) {
            plo[q] = __uint_as_float((unsigned)(acc2[p][q] & 0xffffffffu));
            phi[q] = __uint_as_float((unsigned)(acc2[p][q] >> 32));
        }
        *reinterpret_cast<float4*>(yb + (size_t)(2 * p)     * H * W) = vlo;
        *reinterpret_cast<float4*>(yb + (size_t)(2 * p + 1) * H * W) = vhi;
    }
}

} // namespace

extern "C" void kernel_launch(void* const* d_in, const int* in_sizes, int n_in,
                              void* d_out, int out_size)
{
    const float* x  = (const float*)d_in[0];   // [1024,64,56,56] f32
    const float* wt = (const float*)d_in[1];   // [32,3,3,64] f32
    float* y = (float*)d_out;                  // [1024,64,56,56] f32

    cudaFuncSetAttribute(shift_conv_kernel,
                         cudaFuncAttributeMaxDynamicSharedMemorySize, SMEM_BYTES);
    dim3 grid(H / TH, 1024, 1);
    shift_conv_kernel<<<grid, NTHR, SMEM_BYTES>>>(x, wt, y);
}